// round 2
// baseline (speedup 1.0000x reference)
#include <cuda_runtime.h>

// GConvLSTM (ChebConv K=1) fused cell + linear head. NPT=2 register blocking:
// each thread computes 2 nodes so every shared-memory weight read is amortized
// over 2 nodes. Head weights (Wl) padded to 12 and read as wide LDS.

#define FIN   8
#define HDIM  32
#define OUTD  9
#define KTOT  (FIN + HDIM)   // 40 floats per (gate, channel) weight row
#define KPAIR (KTOT / 2)     // 20 f32x2 pairs
#define TPB   256
#define NPT   2
#define NPB   (TPB * NPT)    // nodes per block

// ---------------- fast math helpers (MUFU) ----------------
__device__ __forceinline__ float fast_ex2(float x) {
    float r; asm("ex2.approx.f32 %0, %1;" : "=f"(r) : "f"(x)); return r;
}
__device__ __forceinline__ float fast_rcp(float x) {
    float r; asm("rcp.approx.f32 %0, %1;" : "=f"(r) : "f"(x)); return r;
}
__device__ __forceinline__ float sigmoid_f(float v) {
    return fast_rcp(1.0f + fast_ex2(-1.4426950408889634f * v));
}
__device__ __forceinline__ float tanh_f(float v) {
    return 1.0f - 2.0f * fast_rcp(1.0f + fast_ex2(2.8853900817779268f * v));
}

// ---------------- packed f32x2 helpers ----------------
__device__ __forceinline__ void ffma2(unsigned long long& acc,
                                      unsigned long long a,
                                      unsigned long long b) {
    asm("fma.rn.f32x2 %0, %1, %2, %0;" : "+l"(acc) : "l"(a), "l"(b));
}
__device__ __forceinline__ void unpack2(unsigned long long v, float& lo, float& hi) {
    unsigned int a, b;
    asm("mov.b64 {%0, %1}, %2;" : "=r"(a), "=r"(b) : "l"(v));
    lo = __uint_as_float(a);
    hi = __uint_as_float(b);
}
__device__ __forceinline__ unsigned long long pack2(float lo, float hi) {
    unsigned long long v;
    asm("mov.b64 %0, {%1, %2};" : "=l"(v) : "r"(__float_as_uint(lo)), "r"(__float_as_uint(hi)));
    return v;
}

struct Params {
    const float* x;
    const float* h;
    const float* c;
    const float* Wx[4];   // i, f, c, o   shape [FIN, H] row-major
    const float* bx[4];
    const float* Wh[4];   // [H, H]
    const float* bh[4];
    const float* b[4];
    const float* wc[4];   // peephole; wc[2] == nullptr (cell gate has none)
    const float* Wl;      // [H, OUT]
    const float* bl;      // [OUT]
    float* y;             // [N, OUT]
    float* h0;            // [N, H]
    float* c0;            // [N, H]
    int N;
};

__global__ void __launch_bounds__(TPB, 2)
gconv_lstm_kernel(Params P) {
    // ---- shared weight staging (transposed so channel j is a contiguous row) ----
    __shared__ float sW[4][HDIM][KTOT];            // [gate][j][k]
    __shared__ float sB[4][HDIM];                  // bx + bh + b combined
    __shared__ float sC[4][HDIM];                  // peephole (gate 2 = zeros)
    __shared__ __align__(16) float sL[HDIM][12];   // Wl rows padded 9 -> 12
    __shared__ __align__(16) float sBl[12];

    const int tid = threadIdx.x;

    for (int idx = tid; idx < 4 * FIN * HDIM; idx += TPB) {
        int g = idx / (FIN * HDIM);
        int r = idx % (FIN * HDIM);
        int k = r / HDIM, j = r % HDIM;
        sW[g][j][k] = P.Wx[g][k * HDIM + j];
    }
    for (int idx = tid; idx < 4 * HDIM * HDIM; idx += TPB) {
        int g = idx / (HDIM * HDIM);
        int r = idx % (HDIM * HDIM);
        int k = r / HDIM, j = r % HDIM;
        sW[g][j][FIN + k] = P.Wh[g][k * HDIM + j];
    }
    for (int idx = tid; idx < 4 * HDIM; idx += TPB) {
        int g = idx / HDIM, j = idx % HDIM;
        sB[g][j] = P.bx[g][j] + P.bh[g][j] + P.b[g][j];
        sC[g][j] = (g == 2) ? 0.0f : P.wc[g][j];
    }
    for (int idx = tid; idx < HDIM * 12; idx += TPB) {
        int j = idx / 12, m = idx % 12;
        sL[j][m] = (m < OUTD) ? P.Wl[j * OUTD + m] : 0.0f;
    }
    if (tid < 12) sBl[tid] = (tid < OUTD) ? P.bl[tid] : 0.0f;
    __syncthreads();

    const int n0 = blockIdx.x * NPB + tid;
    if (n0 >= P.N) return;
    int n[NPT];
    n[0] = n0;
    n[1] = n0 + TPB;
    const bool v1 = (n[1] < P.N);
    if (!v1) n[1] = n[0];   // duplicate compute, skip store

    // ---- load x (8) and h (32) per node as f32x2 pairs ----
    unsigned long long in2[NPT][KPAIR];
#pragma unroll
    for (int p = 0; p < NPT; p++) {
        const ulonglong2* xp = (const ulonglong2*)(P.x + (size_t)n[p] * FIN);
        ulonglong2 t0 = xp[0], t1 = xp[1];
        in2[p][0] = t0.x; in2[p][1] = t0.y; in2[p][2] = t1.x; in2[p][3] = t1.y;
        const ulonglong2* hp = (const ulonglong2*)(P.h + (size_t)n[p] * HDIM);
#pragma unroll
        for (int i = 0; i < 8; i++) {
            ulonglong2 t = hp[i];
            in2[p][4 + 2 * i] = t.x;
            in2[p][5 + 2 * i] = t.y;
        }
    }

    // y accumulators packed as f32x2 (5 pairs = 9 outputs + 1 pad)
    unsigned long long yacc[NPT][5];
    {
        const unsigned long long* blp = (const unsigned long long*)sBl;
#pragma unroll
        for (int m = 0; m < 5; m++) {
            yacc[0][m] = blp[m];
            yacc[1][m] = blp[m];
        }
    }

#pragma unroll 1
    for (int jq = 0; jq < HDIM / 4; jq++) {
        float cj[NPT][4];
#pragma unroll
        for (int p = 0; p < NPT; p++) {
            float4 cq = ((const float4*)(P.c + (size_t)n[p] * HDIM))[jq];
            cj[p][0] = cq.x; cj[p][1] = cq.y; cj[p][2] = cq.z; cj[p][3] = cq.w;
        }
        float h0q[NPT][4], c0q[NPT][4];

#pragma unroll
        for (int u = 0; u < 4; u++) {
            const int j = jq * 4 + u;
            float s[NPT][4];
#pragma unroll
            for (int g = 0; g < 4; g++) {
                const ulonglong2* wr = (const ulonglong2*)&sW[g][j][0];
                unsigned long long a0 = 0ULL, b0 = 0ULL, a1 = 0ULL, b1 = 0ULL;
#pragma unroll
                for (int kk = 0; kk < KPAIR / 2; kk++) {   // 10 LDS.128 serve both nodes
                    ulonglong2 w = wr[kk];
                    ffma2(a0, in2[0][2 * kk + 0], w.x);
                    ffma2(b0, in2[0][2 * kk + 1], w.y);
                    ffma2(a1, in2[1][2 * kk + 0], w.x);
                    ffma2(b1, in2[1][2 * kk + 1], w.y);
                }
                float l0, h0f, l1, h1f;
                unpack2(a0, l0, h0f); unpack2(b0, l1, h1f);
                s[0][g] = (l0 + h0f) + (l1 + h1f) + sB[g][j];
                unpack2(a1, l0, h0f); unpack2(b1, l1, h1f);
                s[1][g] = (l0 + h0f) + (l1 + h1f) + sB[g][j];
            }
            // head weights for channel j (shared by both nodes)
            const ulonglong2* lwv = (const ulonglong2*)&sL[j][0];
            ulonglong2 lw01 = lwv[0], lw23 = lwv[1];
            unsigned long long lw4 = ((const unsigned long long*)&sL[j][8])[0];
            const float c0g = sC[0][j], c1g = sC[1][j], c3g = sC[3][j];

#pragma unroll
            for (int p = 0; p < NPT; p++) {
                const float cv = cj[p][u];
                float ig = sigmoid_f(s[p][0] + c0g * cv);
                float fg = sigmoid_f(s[p][1] + c1g * cv);
                float tg = tanh_f(s[p][2]);
                float cc = fg * cv + ig * tg;
                float og = sigmoid_f(s[p][3] + c3g * cc);
                float hh = og * tanh_f(cc);
                c0q[p][u] = cc;
                h0q[p][u] = hh;
                unsigned long long rr = pack2(fmaxf(hh, 0.0f), fmaxf(hh, 0.0f));
                ffma2(yacc[p][0], rr, lw01.x);
                ffma2(yacc[p][1], rr, lw01.y);
                ffma2(yacc[p][2], rr, lw23.x);
                ffma2(yacc[p][3], rr, lw23.y);
                ffma2(yacc[p][4], rr, lw4);
            }
        }
        // flush h0 / c0 quads
        ((float4*)(P.h0 + (size_t)n[0] * HDIM))[jq] =
            make_float4(h0q[0][0], h0q[0][1], h0q[0][2], h0q[0][3]);
        ((float4*)(P.c0 + (size_t)n[0] * HDIM))[jq] =
            make_float4(c0q[0][0], c0q[0][1], c0q[0][2], c0q[0][3]);
        if (v1) {
            ((float4*)(P.h0 + (size_t)n[1] * HDIM))[jq] =
                make_float4(h0q[1][0], h0q[1][1], h0q[1][2], h0q[1][3]);
            ((float4*)(P.c0 + (size_t)n[1] * HDIM))[jq] =
                make_float4(c0q[1][0], c0q[1][1], c0q[1][2], c0q[1][3]);
        }
    }

    // ---- store y ----
    {
        float* oy = P.y + (size_t)n[0] * OUTD;
        float a, b;
#pragma unroll
        for (int m = 0; m < 4; m++) {
            unpack2(yacc[0][m], a, b);
            oy[2 * m] = a; oy[2 * m + 1] = b;
        }
        unpack2(yacc[0][4], a, b);
        oy[8] = a;
        if (v1) {
            float* oy1 = P.y + (size_t)n[1] * OUTD;
#pragma unroll
            for (int m = 0; m < 4; m++) {
                unpack2(yacc[1][m], a, b);
                oy1[2 * m] = a; oy1[2 * m + 1] = b;
            }
            unpack2(yacc[1][4], a, b);
            oy1[8] = a;
        }
    }
}

extern "C" void kernel_launch(void* const* d_in, const int* in_sizes, int n_in,
                              void* d_out, int out_size) {
    (void)n_in; (void)out_size;
    Params P;
    P.x = (const float*)d_in[0];
    // d_in[1] = edge_index, d_in[2] = edge_weight: unused (ChebConv K=1)
    P.h = (const float*)d_in[3];
    P.c = (const float*)d_in[4];
    const int wx_idx[4] = {5, 11, 17, 22};   // gate order: i, f, c, o
    for (int g = 0; g < 4; g++) {
        int base = wx_idx[g];
        P.Wx[g] = (const float*)d_in[base + 0];
        P.bx[g] = (const float*)d_in[base + 1];
        P.Wh[g] = (const float*)d_in[base + 2];
        P.bh[g] = (const float*)d_in[base + 3];
        P.b[g]  = (const float*)d_in[base + 4];
        P.wc[g] = (g == 2) ? nullptr : (const float*)d_in[base + 5];
    }
    P.Wl = (const float*)d_in[28];
    P.bl = (const float*)d_in[29];

    const int N = in_sizes[0] / FIN;
    P.N = N;
    float* out = (float*)d_out;
    P.y  = out;
    P.h0 = out + (size_t)N * OUTD;
    P.c0 = out + (size_t)N * (OUTD + HDIM);

    const int grid = (N + NPB - 1) / NPB;
    gconv_lstm_kernel<<<grid, TPB>>>(P);
}

// round 3
// speedup vs baseline: 1.1006x; 1.1006x over previous
#include <cuda_runtime.h>

// GConvLSTM (ChebConv K=1) fused cell + linear head.
// NPT=2 register blocking with a 255-register budget (TPB=128, no occupancy
// cap) so nothing spills: each broadcast weight LDS.128 feeds 4 FFMA2.

#define FIN   8
#define HDIM  32
#define OUTD  9
#define KTOT  (FIN + HDIM)   // 40 floats per (gate, channel) weight row
#define KPAIR (KTOT / 2)     // 20 f32x2 pairs
#define TPB   128
#define NPT   2
#define NPB   (TPB * NPT)    // nodes per block

// ---------------- fast math helpers (MUFU) ----------------
__device__ __forceinline__ float fast_ex2(float x) {
    float r; asm("ex2.approx.f32 %0, %1;" : "=f"(r) : "f"(x)); return r;
}
__device__ __forceinline__ float fast_rcp(float x) {
    float r; asm("rcp.approx.f32 %0, %1;" : "=f"(r) : "f"(x)); return r;
}
__device__ __forceinline__ float sigmoid_f(float v) {
    return fast_rcp(1.0f + fast_ex2(-1.4426950408889634f * v));
}
__device__ __forceinline__ float tanh_f(float v) {
    return 1.0f - 2.0f * fast_rcp(1.0f + fast_ex2(2.8853900817779268f * v));
}

// ---------------- packed f32x2 helpers ----------------
__device__ __forceinline__ void ffma2(unsigned long long& acc,
                                      unsigned long long a,
                                      unsigned long long b) {
    asm("fma.rn.f32x2 %0, %1, %2, %0;" : "+l"(acc) : "l"(a), "l"(b));
}
__device__ __forceinline__ void unpack2(unsigned long long v, float& lo, float& hi) {
    unsigned int a, b;
    asm("mov.b64 {%0, %1}, %2;" : "=r"(a), "=r"(b) : "l"(v));
    lo = __uint_as_float(a);
    hi = __uint_as_float(b);
}
__device__ __forceinline__ unsigned long long pack2(float lo, float hi) {
    unsigned long long v;
    asm("mov.b64 %0, {%1, %2};" : "=l"(v) : "r"(__float_as_uint(lo)), "r"(__float_as_uint(hi)));
    return v;
}

struct Params {
    const float* x;
    const float* h;
    const float* c;
    const float* Wx[4];   // i, f, c, o   shape [FIN, H] row-major
    const float* bx[4];
    const float* Wh[4];   // [H, H]
    const float* bh[4];
    const float* b[4];
    const float* wc[4];   // peephole; wc[2] == nullptr (cell gate has none)
    const float* Wl;      // [H, OUT]
    const float* bl;      // [OUT]
    float* y;             // [N, OUT]
    float* h0;            // [N, H]
    float* c0;            // [N, H]
    int N;
};

__global__ void __launch_bounds__(TPB)
gconv_lstm_kernel(Params P) {
    // ---- shared weight staging (transposed so channel j is a contiguous row) ----
    __shared__ float sW[4][HDIM][KTOT];            // [gate][j][k]
    __shared__ float sB[4][HDIM];                  // bx + bh + b combined
    __shared__ float sC[4][HDIM];                  // peephole (gate 2 = zeros)
    __shared__ __align__(16) float sL[HDIM][12];   // Wl rows padded 9 -> 12
    __shared__ __align__(16) float sBl[12];

    const int tid = threadIdx.x;

    for (int idx = tid; idx < 4 * FIN * HDIM; idx += TPB) {
        int g = idx / (FIN * HDIM);
        int r = idx % (FIN * HDIM);
        int k = r / HDIM, j = r % HDIM;
        sW[g][j][k] = P.Wx[g][k * HDIM + j];
    }
    for (int idx = tid; idx < 4 * HDIM * HDIM; idx += TPB) {
        int g = idx / (HDIM * HDIM);
        int r = idx % (HDIM * HDIM);
        int k = r / HDIM, j = r % HDIM;
        sW[g][j][FIN + k] = P.Wh[g][k * HDIM + j];
    }
    for (int idx = tid; idx < 4 * HDIM; idx += TPB) {
        int g = idx / HDIM, j = idx % HDIM;
        sB[g][j] = P.bx[g][j] + P.bh[g][j] + P.b[g][j];
        sC[g][j] = (g == 2) ? 0.0f : P.wc[g][j];
    }
    for (int idx = tid; idx < HDIM * 12; idx += TPB) {
        int j = idx / 12, m = idx % 12;
        sL[j][m] = (m < OUTD) ? P.Wl[j * OUTD + m] : 0.0f;
    }
    if (tid < 12) sBl[tid] = (tid < OUTD) ? P.bl[tid] : 0.0f;
    __syncthreads();

    const int n0 = blockIdx.x * NPB + tid;
    if (n0 >= P.N) return;
    int n[NPT];
    n[0] = n0;
    n[1] = n0 + TPB;
    const bool v1 = (n[1] < P.N);
    if (!v1) n[1] = n[0];   // duplicate compute, skip store

    // ---- load x (8) and h (32) per node as f32x2 pairs ----
    unsigned long long in2[NPT][KPAIR];
#pragma unroll
    for (int p = 0; p < NPT; p++) {
        const ulonglong2* xp = (const ulonglong2*)(P.x + (size_t)n[p] * FIN);
        ulonglong2 t0 = xp[0], t1 = xp[1];
        in2[p][0] = t0.x; in2[p][1] = t0.y; in2[p][2] = t1.x; in2[p][3] = t1.y;
        const ulonglong2* hp = (const ulonglong2*)(P.h + (size_t)n[p] * HDIM);
#pragma unroll
        for (int i = 0; i < 8; i++) {
            ulonglong2 t = hp[i];
            in2[p][4 + 2 * i] = t.x;
            in2[p][5 + 2 * i] = t.y;
        }
    }

    // y accumulators packed as f32x2 (5 pairs = 9 outputs + 1 pad)
    unsigned long long yacc[NPT][5];
    {
        const unsigned long long* blp = (const unsigned long long*)sBl;
#pragma unroll
        for (int m = 0; m < 5; m++) {
            yacc[0][m] = blp[m];
            yacc[1][m] = blp[m];
        }
    }

#pragma unroll 1
    for (int jq = 0; jq < HDIM / 4; jq++) {
        float cj[NPT][4];
#pragma unroll
        for (int p = 0; p < NPT; p++) {
            float4 cq = ((const float4*)(P.c + (size_t)n[p] * HDIM))[jq];
            cj[p][0] = cq.x; cj[p][1] = cq.y; cj[p][2] = cq.z; cj[p][3] = cq.w;
        }
        float h0q[NPT][4], c0q[NPT][4];

#pragma unroll
        for (int u = 0; u < 4; u++) {
            const int j = jq * 4 + u;
            float s[NPT][4];
#pragma unroll
            for (int g = 0; g < 4; g++) {
                const ulonglong2* wr = (const ulonglong2*)&sW[g][j][0];
                unsigned long long a0 = 0ULL, b0 = 0ULL, a1 = 0ULL, b1 = 0ULL;
#pragma unroll
                for (int kk = 0; kk < KPAIR / 2; kk++) {   // 10 LDS.128 serve both nodes
                    ulonglong2 w = wr[kk];
                    ffma2(a0, in2[0][2 * kk + 0], w.x);
                    ffma2(b0, in2[0][2 * kk + 1], w.y);
                    ffma2(a1, in2[1][2 * kk + 0], w.x);
                    ffma2(b1, in2[1][2 * kk + 1], w.y);
                }
                float l0, h0f, l1, h1f;
                unpack2(a0, l0, h0f); unpack2(b0, l1, h1f);
                s[0][g] = (l0 + h0f) + (l1 + h1f) + sB[g][j];
                unpack2(a1, l0, h0f); unpack2(b1, l1, h1f);
                s[1][g] = (l0 + h0f) + (l1 + h1f) + sB[g][j];
            }
            // head weights for channel j (shared by both nodes)
            const ulonglong2* lwv = (const ulonglong2*)&sL[j][0];
            ulonglong2 lw01 = lwv[0], lw23 = lwv[1];
            unsigned long long lw4 = ((const unsigned long long*)&sL[j][8])[0];
            const float c0g = sC[0][j], c1g = sC[1][j], c3g = sC[3][j];

#pragma unroll
            for (int p = 0; p < NPT; p++) {
                const float cv = cj[p][u];
                float ig = sigmoid_f(s[p][0] + c0g * cv);
                float fg = sigmoid_f(s[p][1] + c1g * cv);
                float tg = tanh_f(s[p][2]);
                float cc = fg * cv + ig * tg;
                float og = sigmoid_f(s[p][3] + c3g * cc);
                float hh = og * tanh_f(cc);
                c0q[p][u] = cc;
                h0q[p][u] = hh;
                float r = fmaxf(hh, 0.0f);
                unsigned long long rr = pack2(r, r);
                ffma2(yacc[p][0], rr, lw01.x);
                ffma2(yacc[p][1], rr, lw01.y);
                ffma2(yacc[p][2], rr, lw23.x);
                ffma2(yacc[p][3], rr, lw23.y);
                ffma2(yacc[p][4], rr, lw4);
            }
        }
        // flush h0 / c0 quads
        ((float4*)(P.h0 + (size_t)n[0] * HDIM))[jq] =
            make_float4(h0q[0][0], h0q[0][1], h0q[0][2], h0q[0][3]);
        ((float4*)(P.c0 + (size_t)n[0] * HDIM))[jq] =
            make_float4(c0q[0][0], c0q[0][1], c0q[0][2], c0q[0][3]);
        if (v1) {
            ((float4*)(P.h0 + (size_t)n[1] * HDIM))[jq] =
                make_float4(h0q[1][0], h0q[1][1], h0q[1][2], h0q[1][3]);
            ((float4*)(P.c0 + (size_t)n[1] * HDIM))[jq] =
                make_float4(c0q[1][0], c0q[1][1], c0q[1][2], c0q[1][3]);
        }
    }

    // ---- store y ----
    {
        float* oy = P.y + (size_t)n[0] * OUTD;
        float a, b;
#pragma unroll
        for (int m = 0; m < 4; m++) {
            unpack2(yacc[0][m], a, b);
            oy[2 * m] = a; oy[2 * m + 1] = b;
        }
        unpack2(yacc[0][4], a, b);
        oy[8] = a;
        if (v1) {
            float* oy1 = P.y + (size_t)n[1] * OUTD;
#pragma unroll
            for (int m = 0; m < 4; m++) {
                unpack2(yacc[1][m], a, b);
                oy1[2 * m] = a; oy1[2 * m + 1] = b;
            }
            unpack2(yacc[1][4], a, b);
            oy1[8] = a;
        }
    }
}

extern "C" void kernel_launch(void* const* d_in, const int* in_sizes, int n_in,
                              void* d_out, int out_size) {
    (void)n_in; (void)out_size;
    Params P;
    P.x = (const float*)d_in[0];
    // d_in[1] = edge_index, d_in[2] = edge_weight: unused (ChebConv K=1)
    P.h = (const float*)d_in[3];
    P.c = (const float*)d_in[4];
    const int wx_idx[4] = {5, 11, 17, 22};   // gate order: i, f, c, o
    for (int g = 0; g < 4; g++) {
        int base = wx_idx[g];
        P.Wx[g] = (const float*)d_in[base + 0];
        P.bx[g] = (const float*)d_in[base + 1];
        P.Wh[g] = (const float*)d_in[base + 2];
        P.bh[g] = (const float*)d_in[base + 3];
        P.b[g]  = (const float*)d_in[base + 4];
        P.wc[g] = (g == 2) ? nullptr : (const float*)d_in[base + 5];
    }
    P.Wl = (const float*)d_in[28];
    P.bl = (const float*)d_in[29];

    const int N = in_sizes[0] / FIN;
    P.N = N;
    float* out = (float*)d_out;
    P.y  = out;
    P.h0 = out + (size_t)N * OUTD;
    P.c0 = out + (size_t)N * (OUTD + HDIM);

    const int grid = (N + NPB - 1) / NPB;
    gconv_lstm_kernel<<<grid, TPB>>>(P);
}

// round 4
// speedup vs baseline: 1.7094x; 1.5532x over previous
#include <cuda_runtime.h>

// GConvLSTM (ChebConv K=1) fused cell + linear head.
// Weights live in __constant__ memory: warp-uniform weight operands come in
// through the uniform-constant port (LDCU, floor 1/SMSP) instead of the shared
// crossbar (broadcast LDS.128 = 4 cyc for 16 useful bytes), leaving the fma
// pipe as the binding resource. A prep kernel packs weights into a __device__
// staging struct; cudaMemcpyToSymbolAsync (D2D, capturable) loads the bank.

#define FIN   8
#define HDIM  32
#define OUTD  9
#define KTOT  (FIN + HDIM)   // 40 floats per (gate, channel) weight row
#define KPAIR (KTOT / 2)     // 20 f32x2 pairs
#define TPB   128
#define NPT   2
#define NPB   (TPB * NPT)    // nodes per block

// ---------------- constant-packed parameters ----------------
struct __align__(16) CPack {
    float W[4][HDIM][KTOT];   // [gate][j][k]: k<8 = Wx col j, k>=8 = Wh col j
    float B[4][HDIM];         // bx + bh + b combined
    float C[4][HDIM];         // peephole (gate 2 = zeros)
    float L[HDIM][12];        // Wl rows padded 9 -> 12
    float Bl[12];
};

__constant__ __align__(16) CPack cPK;
__device__   __align__(16) CPack g_stage;

// ---------------- fast math helpers (MUFU) ----------------
__device__ __forceinline__ float fast_ex2(float x) {
    float r; asm("ex2.approx.f32 %0, %1;" : "=f"(r) : "f"(x)); return r;
}
__device__ __forceinline__ float fast_rcp(float x) {
    float r; asm("rcp.approx.f32 %0, %1;" : "=f"(r) : "f"(x)); return r;
}
__device__ __forceinline__ float sigmoid_f(float v) {
    return fast_rcp(1.0f + fast_ex2(-1.4426950408889634f * v));
}
__device__ __forceinline__ float tanh_f(float v) {
    return 1.0f - 2.0f * fast_rcp(1.0f + fast_ex2(2.8853900817779268f * v));
}

// ---------------- packed f32x2 helpers ----------------
__device__ __forceinline__ void ffma2(unsigned long long& acc,
                                      unsigned long long a,
                                      unsigned long long b) {
    asm("fma.rn.f32x2 %0, %1, %2, %0;" : "+l"(acc) : "l"(a), "l"(b));
}
__device__ __forceinline__ void unpack2(unsigned long long v, float& lo, float& hi) {
    unsigned int a, b;
    asm("mov.b64 {%0, %1}, %2;" : "=r"(a), "=r"(b) : "l"(v));
    lo = __uint_as_float(a);
    hi = __uint_as_float(b);
}
__device__ __forceinline__ unsigned long long pack2(float lo, float hi) {
    unsigned long long v;
    asm("mov.b64 %0, {%1, %2};" : "=l"(v) : "r"(__float_as_uint(lo)), "r"(__float_as_uint(hi)));
    return v;
}

struct PrepArgs {
    const float* Wx[4];
    const float* bx[4];
    const float* Wh[4];
    const float* bh[4];
    const float* b[4];
    const float* wc[4];   // wc[2] unused
    const float* Wl;
    const float* bl;
};

__global__ void prep_kernel(PrepArgs A) {
    const int tid = threadIdx.x;
    // W[g][j][k]
    for (int idx = tid; idx < 4 * HDIM * KTOT; idx += blockDim.x) {
        int g = idx / (HDIM * KTOT);
        int r = idx % (HDIM * KTOT);
        int j = r / KTOT, k = r % KTOT;
        g_stage.W[g][j][k] = (k < FIN) ? A.Wx[g][k * HDIM + j]
                                       : A.Wh[g][(k - FIN) * HDIM + j];
    }
    for (int idx = tid; idx < 4 * HDIM; idx += blockDim.x) {
        int g = idx / HDIM, j = idx % HDIM;
        g_stage.B[g][j] = A.bx[g][j] + A.bh[g][j] + A.b[g][j];
        g_stage.C[g][j] = (g == 2) ? 0.0f : A.wc[g][j];
    }
    for (int idx = tid; idx < HDIM * 12; idx += blockDim.x) {
        int j = idx / 12, m = idx % 12;
        g_stage.L[j][m] = (m < OUTD) ? A.Wl[j * OUTD + m] : 0.0f;
    }
    if (tid < 12) g_stage.Bl[tid] = (tid < OUTD) ? A.bl[tid] : 0.0f;
}

struct Params {
    const float* x;
    const float* h;
    const float* c;
    float* y;
    float* h0;
    float* c0;
    int N;
};

__global__ void __launch_bounds__(TPB, 3)
gconv_lstm_kernel(Params P) {
    const int tid = threadIdx.x;
    const int n0 = blockIdx.x * NPB + tid;
    if (n0 >= P.N) return;
    int n[NPT];
    n[0] = n0;
    n[1] = n0 + TPB;
    const bool v1 = (n[1] < P.N);
    if (!v1) n[1] = n[0];   // duplicate compute, skip store

    // ---- load x (8) and h (32) per node as f32x2 pairs ----
    unsigned long long in2[NPT][KPAIR];
#pragma unroll
    for (int p = 0; p < NPT; p++) {
        const ulonglong2* xp = (const ulonglong2*)(P.x + (size_t)n[p] * FIN);
        ulonglong2 t0 = xp[0], t1 = xp[1];
        in2[p][0] = t0.x; in2[p][1] = t0.y; in2[p][2] = t1.x; in2[p][3] = t1.y;
        const ulonglong2* hp = (const ulonglong2*)(P.h + (size_t)n[p] * HDIM);
#pragma unroll
        for (int i = 0; i < 8; i++) {
            ulonglong2 t = hp[i];
            in2[p][4 + 2 * i] = t.x;
            in2[p][5 + 2 * i] = t.y;
        }
    }

    // y accumulators packed as f32x2 (5 pairs = 9 outputs + 1 pad)
    unsigned long long yacc[NPT][5];
    {
        const unsigned long long* blp = (const unsigned long long*)cPK.Bl;
#pragma unroll
        for (int m = 0; m < 5; m++) {
            yacc[0][m] = blp[m];
            yacc[1][m] = blp[m];
        }
    }

#pragma unroll 1
    for (int jq = 0; jq < HDIM / 4; jq++) {
        float cj[NPT][4];
#pragma unroll
        for (int p = 0; p < NPT; p++) {
            float4 cq = ((const float4*)(P.c + (size_t)n[p] * HDIM))[jq];
            cj[p][0] = cq.x; cj[p][1] = cq.y; cj[p][2] = cq.z; cj[p][3] = cq.w;
        }
        float h0q[NPT][4], c0q[NPT][4];

#pragma unroll
        for (int u = 0; u < 4; u++) {
            const int j = jq * 4 + u;
            float s[NPT][4];
#pragma unroll
            for (int g = 0; g < 4; g++) {
                const ulonglong2* wr = (const ulonglong2*)&cPK.W[g][j][0];
                unsigned long long a0 = 0ULL, b0 = 0ULL, a1 = 0ULL, b1 = 0ULL;
#pragma unroll
                for (int kk = 0; kk < KPAIR / 2; kk++) {   // uniform const loads
                    ulonglong2 w = wr[kk];
                    ffma2(a0, in2[0][2 * kk + 0], w.x);
                    ffma2(b0, in2[0][2 * kk + 1], w.y);
                    ffma2(a1, in2[1][2 * kk + 0], w.x);
                    ffma2(b1, in2[1][2 * kk + 1], w.y);
                }
                float l0, h0f, l1, h1f;
                unpack2(a0, l0, h0f); unpack2(b0, l1, h1f);
                s[0][g] = (l0 + h0f) + (l1 + h1f) + cPK.B[g][j];
                unpack2(a1, l0, h0f); unpack2(b1, l1, h1f);
                s[1][g] = (l0 + h0f) + (l1 + h1f) + cPK.B[g][j];
            }
            // head weights for channel j (uniform const loads)
            const ulonglong2* lwv = (const ulonglong2*)&cPK.L[j][0];
            ulonglong2 lw01 = lwv[0], lw23 = lwv[1];
            unsigned long long lw4 = ((const unsigned long long*)&cPK.L[j][8])[0];
            const float c0g = cPK.C[0][j], c1g = cPK.C[1][j], c3g = cPK.C[3][j];

#pragma unroll
            for (int p = 0; p < NPT; p++) {
                const float cv = cj[p][u];
                float ig = sigmoid_f(s[p][0] + c0g * cv);
                float fg = sigmoid_f(s[p][1] + c1g * cv);
                float tg = tanh_f(s[p][2]);
                float cc = fg * cv + ig * tg;
                float og = sigmoid_f(s[p][3] + c3g * cc);
                float hh = og * tanh_f(cc);
                c0q[p][u] = cc;
                h0q[p][u] = hh;
                float r = fmaxf(hh, 0.0f);
                unsigned long long rr = pack2(r, r);
                ffma2(yacc[p][0], rr, lw01.x);
                ffma2(yacc[p][1], rr, lw01.y);
                ffma2(yacc[p][2], rr, lw23.x);
                ffma2(yacc[p][3], rr, lw23.y);
                ffma2(yacc[p][4], rr, lw4);
            }
        }
        // flush h0 / c0 quads
        ((float4*)(P.h0 + (size_t)n[0] * HDIM))[jq] =
            make_float4(h0q[0][0], h0q[0][1], h0q[0][2], h0q[0][3]);
        ((float4*)(P.c0 + (size_t)n[0] * HDIM))[jq] =
            make_float4(c0q[0][0], c0q[0][1], c0q[0][2], c0q[0][3]);
        if (v1) {
            ((float4*)(P.h0 + (size_t)n[1] * HDIM))[jq] =
                make_float4(h0q[1][0], h0q[1][1], h0q[1][2], h0q[1][3]);
            ((float4*)(P.c0 + (size_t)n[1] * HDIM))[jq] =
                make_float4(c0q[1][0], c0q[1][1], c0q[1][2], c0q[1][3]);
        }
    }

    // ---- store y ----
    {
        float* oy = P.y + (size_t)n[0] * OUTD;
        float a, b;
#pragma unroll
        for (int m = 0; m < 4; m++) {
            unpack2(yacc[0][m], a, b);
            oy[2 * m] = a; oy[2 * m + 1] = b;
        }
        unpack2(yacc[0][4], a, b);
        oy[8] = a;
        if (v1) {
            float* oy1 = P.y + (size_t)n[1] * OUTD;
#pragma unroll
            for (int m = 0; m < 4; m++) {
                unpack2(yacc[1][m], a, b);
                oy1[2 * m] = a; oy1[2 * m + 1] = b;
            }
            unpack2(yacc[1][4], a, b);
            oy1[8] = a;
        }
    }
}

extern "C" void kernel_launch(void* const* d_in, const int* in_sizes, int n_in,
                              void* d_out, int out_size) {
    (void)n_in; (void)out_size;

    PrepArgs A;
    const int wx_idx[4] = {5, 11, 17, 22};   // gate order: i, f, c, o
    for (int g = 0; g < 4; g++) {
        int base = wx_idx[g];
        A.Wx[g] = (const float*)d_in[base + 0];
        A.bx[g] = (const float*)d_in[base + 1];
        A.Wh[g] = (const float*)d_in[base + 2];
        A.bh[g] = (const float*)d_in[base + 3];
        A.b[g]  = (const float*)d_in[base + 4];
        A.wc[g] = (g == 2) ? A.b[g] : (const float*)d_in[base + 5];  // dummy for gate c
    }
    A.Wl = (const float*)d_in[28];
    A.bl = (const float*)d_in[29];

    Params P;
    P.x = (const float*)d_in[0];
    // d_in[1] = edge_index, d_in[2] = edge_weight: unused (ChebConv K=1)
    P.h = (const float*)d_in[3];
    P.c = (const float*)d_in[4];

    const int N = in_sizes[0] / FIN;
    P.N = N;
    float* out = (float*)d_out;
    P.y  = out;
    P.h0 = out + (size_t)N * OUTD;
    P.c0 = out + (size_t)N * (OUTD + HDIM);

    // 1) pack weights into staging struct; 2) copy into the constant bank
    prep_kernel<<<1, 256>>>(A);
    void* stage_ptr = nullptr;
    cudaGetSymbolAddress(&stage_ptr, g_stage);
    cudaMemcpyToSymbolAsync(cPK, stage_ptr, sizeof(CPack), 0,
                            cudaMemcpyDeviceToDevice, 0);

    const int grid = (N + NPB - 1) / NPB;
    gconv_lstm_kernel<<<grid, TPB>>>(P);
}